// round 16
// baseline (speedup 1.0000x reference)
#include <cuda_runtime.h>
#include <cuda_fp16.h>
#include <math.h>
#include <stdint.h>

#define N_NODES 100000
#define E_EDGES 3200000
#define F_IN    512
#define F_HID   256
#define F_OUT   40
#define NBLK    391   // ceil(N_NODES/256)

// ---- scratch (static device globals; no runtime allocation) ----
__device__ __align__(16) __half g_sup1h[(size_t)N_NODES * F_HID]; // x @ W1 (fp16)
__device__ __align__(16) __half g_w1t[(size_t)F_HID * F_IN];      // W1^T fp16 [N][K]
__device__ __align__(16) __half g_hh[(size_t)N_NODES * F_HID];    // relu(A @ sup1) fp16
__device__ __align__(16) __half g_sup2h[(size_t)N_NODES * F_OUT]; // h @ W2 fp16
__device__ int   g_deg[N_NODES + 1];
__device__ int   g_rowptr[N_NODES + 1];
__device__ int   g_cursor[N_NODES];
__device__ int   g_bsum[512];
__device__ int2  g_epack[E_EDGES];                  // (src, weight bits), dst-grouped
__device__ int   g_is64;   // 1 if edge_index buffer is actually int64

// ============================================================
// dtype probe: int64 values < 2^32 have all-zero odd int32 words
// ============================================================
__global__ void detect_dtype_kernel(const int* __restrict__ ei) {
    bool allz = true;
    for (int i = threadIdx.x; i < 64; i += 32)
        if (ei[2 * i + 1] != 0) allz = false;
    allz = __all_sync(0xffffffffu, allz);
    if (threadIdx.x == 0) g_is64 = allz ? 1 : 0;
}

__device__ __forceinline__ int load_src(const int* ei, int e, int is64) {
    return is64 ? __ldcs(ei + 2 * (size_t)e) : __ldcs(ei + e);
}
__device__ __forceinline__ int load_dst(const int* ei, int e, int is64) {
    return is64 ? __ldcs(ei + 2 * ((size_t)E_EDGES + e)) : __ldcs(ei + (size_t)E_EDGES + e);
}

// ============================================================
// CSR construction (dst-sorted adjacency, built every launch)
// ============================================================
__global__ void zero_deg_kernel() {
    int i = blockIdx.x * blockDim.x + threadIdx.x;
    if (i <= N_NODES) g_deg[i] = 0;
}

__global__ void hist_kernel(const int* __restrict__ ei) {
    int e = blockIdx.x * blockDim.x + threadIdx.x;
    if (e >= E_EDGES) return;
    int is64 = g_is64;
    unsigned d = (unsigned)load_dst(ei, e, is64);
    if (d < N_NODES) atomicAdd(&g_deg[d], 1);
}

// ---- 3-phase parallel exclusive scan of g_deg -> g_rowptr / g_cursor ----
__global__ void scan_blocks_kernel() {
    int tid = threadIdx.x;
    int i = blockIdx.x * 256 + tid;
    int v = (i < N_NODES) ? g_deg[i] : 0;
    int lane = tid & 31, w = tid >> 5;
    int x = v;
#pragma unroll
    for (int off = 1; off < 32; off <<= 1) {
        int t = __shfl_up_sync(0xffffffffu, x, off);
        if (lane >= off) x += t;
    }
    __shared__ int ws[8];
    if (lane == 31) ws[w] = x;
    __syncthreads();
    if (w == 0) {
        int y = (lane < 8) ? ws[lane] : 0;
#pragma unroll
        for (int off = 1; off < 8; off <<= 1) {
            int t = __shfl_up_sync(0xffffffffu, y, off);
            if (lane >= off) y += t;
        }
        if (lane < 8) ws[lane] = y;
    }
    __syncthreads();
    int incl = x + (w > 0 ? ws[w - 1] : 0);
    if (i < N_NODES) g_rowptr[i] = incl - v;
    if (tid == 255) g_bsum[blockIdx.x] = incl;
}

__global__ void scan_bsum_kernel() {
    int tid = threadIdx.x;   // 512
    int v = (tid < NBLK) ? g_bsum[tid] : 0;
    int lane = tid & 31, w = tid >> 5;
    int x = v;
#pragma unroll
    for (int off = 1; off < 32; off <<= 1) {
        int t = __shfl_up_sync(0xffffffffu, x, off);
        if (lane >= off) x += t;
    }
    __shared__ int ws[16];
    if (lane == 31) ws[w] = x;
    __syncthreads();
    if (w == 0) {
        int y = (lane < 16) ? ws[lane] : 0;
#pragma unroll
        for (int off = 1; off < 16; off <<= 1) {
            int t = __shfl_up_sync(0xffffffffu, y, off);
            if (lane >= off) y += t;
        }
        if (lane < 16) ws[lane] = y;
    }
    __syncthreads();
    int incl = x + (w > 0 ? ws[w - 1] : 0);
    if (tid < NBLK) g_bsum[tid] = incl - v;
    if (tid == NBLK - 1) g_rowptr[N_NODES] = incl;
}

__global__ void scan_add_kernel() {
    int i = blockIdx.x * 256 + threadIdx.x;
    if (i < N_NODES) {
        int r = g_rowptr[i] + g_bsum[blockIdx.x];
        g_rowptr[i] = r;
        g_cursor[i] = r;
    }
}

__global__ void fill_kernel(const int* __restrict__ ei,
                            const float* __restrict__ ew) {
    int e = blockIdx.x * blockDim.x + threadIdx.x;
    if (e >= E_EDGES) return;
    int is64 = g_is64;
    unsigned s = (unsigned)load_src(ei, e, is64);
    unsigned d = (unsigned)load_dst(ei, e, is64);
    if (d >= N_NODES || s >= N_NODES) return;
    int p = atomicAdd(&g_cursor[d], 1);
    if (p < E_EDGES)
        __stcs(&g_epack[p], make_int2((int)s, __float_as_int(__ldcs(ew + e))));
}

// ============================================================
// W1 transpose + fp16 convert: g_w1t[n][k] = (half)W1[k][n]
// ============================================================
__global__ void w1t_kernel(const float* __restrict__ W1) {
    int idx = blockIdx.x * 256 + threadIdx.x;   // over 512*256
    if (idx >= F_IN * F_HID) return;
    int k = idx / F_HID, n = idx % F_HID;
    g_w1t[(size_t)n * F_IN + k] = __float2half_rn(W1[idx]);
}

// ============================================================
// GEMM1 (fp16 tensor cores): sup1h = x[100000,512] @ W1[512,256]
// block tile 64x256, BK=32, double-buffered smem pipeline
// (256 threads, 2 blocks/SM — best measured: ~100 us)
// ============================================================
#define LDSM_X4(r0, r1, r2, r3, addr) \
    asm volatile("ldmatrix.sync.aligned.m8n8.x4.shared.b16 {%0,%1,%2,%3}, [%4];" \
        : "=r"(r0), "=r"(r1), "=r"(r2), "=r"(r3) : "r"(addr))

__device__ __forceinline__ void cp_async16(uint32_t dst, const void* src) {
    asm volatile("cp.async.cg.shared.global [%0], [%1], 16;" :: "r"(dst), "l"(src));
}
#define CP_COMMIT() asm volatile("cp.async.commit_group;")
#define CP_WAIT0()  asm volatile("cp.async.wait_group 0;" ::: "memory")

__global__ __launch_bounds__(256) void sgemm1_f16_kernel(const float* __restrict__ A) {
    __shared__ __half As[2][64][32];    //  8 KB
    __shared__ __half Bs[2][256][32];   // 32 KB
    const int A_BUF = 64 * 32 * 2;      // bytes
    const int B_BUF = 256 * 32 * 2;
    int tid = threadIdx.x;
    int warp = tid >> 5, lane = tid & 31;
    int wm = (warp & 1) * 32;      // 2 m-warps
    int wn = (warp >> 1) * 64;     // 4 n-warps
    int blockRow = blockIdx.x * 64;

    float acc[2][8][4];
#pragma unroll
    for (int mt = 0; mt < 2; mt++)
#pragma unroll
        for (int nt = 0; nt < 8; nt++)
#pragma unroll
            for (int q = 0; q < 4; q++) acc[mt][nt][q] = 0.f;

    // staging mapping
    int sm_m = tid >> 2;                 // A row 0..63
    int sm_c = tid & 3;                  // 16B chunk 0..3
    int a_st_off = (sm_m * 32 + (sm_c ^ ((sm_m >> 1) & 3)) * 8) * 2;
    int gm = blockRow + sm_m;
    if (gm >= N_NODES) gm = N_NODES - 1;
    const float* Arow = A + (size_t)gm * F_IN + sm_c * 8;

    uint32_t a_base = (uint32_t)__cvta_generic_to_shared(&As[0][0][0]);
    uint32_t b_base = (uint32_t)__cvta_generic_to_shared(&Bs[0][0][0]);

    // B staging: 4 rows per thread (n = tid>>2 + 64*i), chunk = tid&3
    int b_n0 = tid >> 2;
    uint32_t b_st[4];
    const __half* b_src[4];
#pragma unroll
    for (int i = 0; i < 4; i++) {
        int n = b_n0 + 64 * i;
        b_st[i] = b_base + (uint32_t)((n * 32 + (sm_c ^ ((n >> 1) & 3)) * 8) * 2);
        b_src[i] = &g_w1t[(size_t)n * F_IN + sm_c * 8];
    }

    // ldmatrix per-lane mapping
    int mat = lane >> 3;             // 0..3
    int mrow = lane & 7;
    int a_row_off = (mat & 1) * 8 + mrow;
    int a_chunk   = (mat >> 1);
    int b_row_off = ((mat >> 1) & 1) * 8 + mrow;
    int b_chunk   = (mat & 1);

    // ---- prologue: stage tile 0 ----
    {
        float4 v0 = *(const float4*)(Arow);
        float4 v1 = *(const float4*)(Arow + 4);
        __half2 p0 = __floats2half2_rn(v0.x, v0.y);
        __half2 p1 = __floats2half2_rn(v0.z, v0.w);
        __half2 p2 = __floats2half2_rn(v1.x, v1.y);
        __half2 p3 = __floats2half2_rn(v1.z, v1.w);
        *(uint4*)((char*)&As[0][0][0] + a_st_off) =
            make_uint4(*(uint32_t*)&p0, *(uint32_t*)&p1,
                       *(uint32_t*)&p2, *(uint32_t*)&p3);
#pragma unroll
        for (int i = 0; i < 4; i++) cp_async16(b_st[i], b_src[i]);
        CP_COMMIT();
        CP_WAIT0();
    }
    __syncthreads();

    const int NIT = F_IN / 32;   // 16
    for (int it = 0; it < NIT; it++) {
        int cur = it & 1, nxt = cur ^ 1;
        bool has_next = (it + 1 < NIT);
        float4 na0, na1;
        if (has_next) {
            int k1 = (it + 1) * 32;
            na0 = *(const float4*)(Arow + k1);       // LDG issued early
            na1 = *(const float4*)(Arow + k1 + 4);
#pragma unroll
            for (int i = 0; i < 4; i++)
                cp_async16(b_st[i] + (uint32_t)(nxt * B_BUF), b_src[i] + k1);
            CP_COMMIT();
        }

        // ---- compute on buffer cur ----
        uint32_t ab = a_base + cur * A_BUF;
        uint32_t bb = b_base + cur * B_BUF;
#pragma unroll
        for (int kk = 0; kk < 32; kk += 16) {
            int kc = kk >> 3;                         // 0 or 2
            uint32_t af[2][4];
#pragma unroll
            for (int mt = 0; mt < 2; mt++) {
                int r = wm + mt * 16 + a_row_off;
                int ch = (kc + a_chunk) ^ ((r >> 1) & 3);
                LDSM_X4(af[mt][0], af[mt][1], af[mt][2], af[mt][3],
                        ab + (uint32_t)((r * 32 + ch * 8) * 2));
            }
            uint32_t bf[8][2];
#pragma unroll
            for (int np = 0; np < 4; np++) {
                int n = wn + np * 16 + b_row_off;
                int ch = (kc + b_chunk) ^ ((n >> 1) & 3);
                LDSM_X4(bf[2 * np][0], bf[2 * np][1],
                        bf[2 * np + 1][0], bf[2 * np + 1][1],
                        bb + (uint32_t)((n * 32 + ch * 8) * 2));
            }
#pragma unroll
            for (int mt = 0; mt < 2; mt++)
#pragma unroll
                for (int nt = 0; nt < 8; nt++) {
                    asm volatile(
                        "mma.sync.aligned.m16n8k16.row.col.f32.f16.f16.f32 "
                        "{%0,%1,%2,%3}, {%4,%5,%6,%7}, {%8,%9}, {%0,%1,%2,%3};\n"
                        : "+f"(acc[mt][nt][0]), "+f"(acc[mt][nt][1]),
                          "+f"(acc[mt][nt][2]), "+f"(acc[mt][nt][3])
                        : "r"(af[mt][0]), "r"(af[mt][1]), "r"(af[mt][2]), "r"(af[mt][3]),
                          "r"(bf[nt][0]), "r"(bf[nt][1]));
                }
        }

        if (has_next) {
            __half2 p0 = __floats2half2_rn(na0.x, na0.y);
            __half2 p1 = __floats2half2_rn(na0.z, na0.w);
            __half2 p2 = __floats2half2_rn(na1.x, na1.y);
            __half2 p3 = __floats2half2_rn(na1.z, na1.w);
            *(uint4*)((char*)&As[0][0][0] + nxt * A_BUF + a_st_off) =
                make_uint4(*(uint32_t*)&p0, *(uint32_t*)&p1,
                           *(uint32_t*)&p2, *(uint32_t*)&p3);
            CP_WAIT0();
        }
        __syncthreads();
    }

    int lk = lane & 3, lr = lane >> 2;
#pragma unroll
    for (int mt = 0; mt < 2; mt++)
#pragma unroll
        for (int nt = 0; nt < 8; nt++) {
            int r0 = blockRow + wm + mt * 16 + lr;
            int cn = wn + nt * 8 + lk * 2;
            if (r0 < N_NODES)
                *(__half2*)(&g_sup1h[(size_t)r0 * F_HID + cn]) =
                    __floats2half2_rn(acc[mt][nt][0], acc[mt][nt][1]);
            int r1 = r0 + 8;
            if (r1 < N_NODES)
                *(__half2*)(&g_sup1h[(size_t)r1 * F_HID + cn]) =
                    __floats2half2_rn(acc[mt][nt][2], acc[mt][nt][3]);
        }
}

// ============================================================
// SPMM1 + ReLU: h[d,:] = relu(sum_j w_j * sup1h[src_j,:]),  256 feats fp16
// warp per dst row; 8 feats/lane; 4-edge unroll
// epack streamed (.cs), h stored streamed (.cs) -> keep sup1h L2-resident
// ============================================================
__device__ __forceinline__ void acc8(float* acc, uint4 v, float w) {
    const __half2* h2 = (const __half2*)&v;
#pragma unroll
    for (int i = 0; i < 4; i++) {
        float2 f = __half22float2(h2[i]);
        acc[2 * i]     += w * f.x;
        acc[2 * i + 1] += w * f.y;
    }
}

__global__ __launch_bounds__(256) void spmm1_relu_kernel() {
    int warp = threadIdx.x >> 5, lane = threadIdx.x & 31;
    int d = blockIdx.x * 8 + warp;
    if (d >= N_NODES) return;
    int s = g_rowptr[d], e = g_rowptr[d + 1];
    float acc[8];
#pragma unroll
    for (int i = 0; i < 8; i++) acc[i] = 0.f;
    const uint4* base = (const uint4*)g_sup1h;   // 16B units; row = 32 units
    int j = s;
    for (; j + 3 < e; j += 4) {
        int2 ep[4];
        uint4 v[4];
#pragma unroll
        for (int q = 0; q < 4; q++) ep[q] = __ldcs(&g_epack[j + q]);
#pragma unroll
        for (int q = 0; q < 4; q++)
            v[q] = __ldg(base + (size_t)ep[q].x * (F_HID / 8) + lane);
#pragma unroll
        for (int q = 0; q < 4; q++)
            acc8(acc, v[q], __int_as_float(ep[q].y));
    }
    for (; j < e; j++) {
        int2 e0 = __ldcs(&g_epack[j]);
        uint4 v0 = __ldg(base + (size_t)e0.x * (F_HID / 8) + lane);
        acc8(acc, v0, __int_as_float(e0.y));
    }
    __half2 o[4];
#pragma unroll
    for (int i = 0; i < 4; i++)
        o[i] = __floats2half2_rn(fmaxf(acc[2 * i], 0.f), fmaxf(acc[2 * i + 1], 0.f));
    __stcs((uint4*)(&g_hh[(size_t)d * F_HID + lane * 8]),
           make_uint4(*(uint32_t*)&o[0], *(uint32_t*)&o[1],
                      *(uint32_t*)&o[2], *(uint32_t*)&o[3]));
}

// ============================================================
// GEMM2: sup2h[100000,40] = h[100000,256] @ W2[256,40]  (h fp16)
// 8 rows/warp; hh consumed as uint4 streamed (.cs — single use)
// ============================================================
__global__ __launch_bounds__(256) void gemm2_kernel(const float* __restrict__ W2) {
    __shared__ float sW[F_HID * F_OUT];   // 40 KB
    int tid = threadIdx.x;
    for (int i = tid; i < F_HID * F_OUT; i += 256) sW[i] = W2[i];
    __syncthreads();
    int warp = tid >> 5, lane = tid & 31;
    int r0 = blockIdx.x * 64 + warp * 8;
    if (r0 >= N_NODES) return;
    int rr[8];
#pragma unroll
    for (int i = 0; i < 8; i++) {
        rr[i] = r0 + i;
        if (rr[i] >= N_NODES) rr[i] = N_NODES - 1;
    }
    float a0[8], a1[8];
#pragma unroll
    for (int i = 0; i < 8; i++) { a0[i] = 0.f; a1[i] = 0.f; }
    int l8 = 32 + (lane & 7);
    for (int k0 = 0; k0 < F_HID; k0 += 8) {
        uint4 hv[8];
#pragma unroll
        for (int i = 0; i < 8; i++)
            hv[i] = __ldcs((const uint4*)&g_hh[(size_t)rr[i] * F_HID + k0]);
#pragma unroll
        for (int kk = 0; kk < 8; kk += 2) {
            float b00 = sW[(k0 + kk) * F_OUT + lane];
            float b01 = sW[(k0 + kk) * F_OUT + l8];
            float b10 = sW[(k0 + kk + 1) * F_OUT + lane];
            float b11 = sW[(k0 + kk + 1) * F_OUT + l8];
#pragma unroll
            for (int i = 0; i < 8; i++) {
                __half2 h2 = ((const __half2*)&hv[i])[kk >> 1];
                float2 hf = __half22float2(h2);
                a0[i] += hf.x * b00 + hf.y * b10;
                a1[i] += hf.x * b01 + hf.y * b11;
            }
        }
    }
#pragma unroll
    for (int i = 0; i < 8; i++) {
        int r = r0 + i;
        if (r < N_NODES) {
            g_sup2h[(size_t)r * F_OUT + lane] = __float2half_rn(a0[i]);
            if (lane < 8) g_sup2h[(size_t)r * F_OUT + 32 + lane] = __float2half_rn(a1[i]);
        }
    }
}

// ============================================================
// Fused SPMM2 + log_softmax: warp per dst row (sup2 fp16)
// lane c (<20) covers classes {2c, 2c+1}; epack streamed (.cs)
// ============================================================
__global__ __launch_bounds__(256) void spmm2_lsm_kernel(float* __restrict__ out) {
    int warp = threadIdx.x >> 5, lane = threadIdx.x & 31;
    int r = blockIdx.x * 8 + warp;
    if (r >= N_NODES) return;
    int s = g_rowptr[r], e = g_rowptr[r + 1];
    bool act = (lane < F_OUT / 2);     // 20 active lanes
    int c2 = lane * 2;                 // class pair base
    float a0 = 0.f, a1 = 0.f;
    int j = s;
    for (; j + 1 < e; j += 2) {
        int2 e0 = __ldcs(&g_epack[j]), e1 = __ldcs(&g_epack[j + 1]);
        float w0 = __int_as_float(e0.y), w1 = __int_as_float(e1.y);
        if (act) {
            __half2 v0 = __ldg((const __half2*)&g_sup2h[(size_t)e0.x * F_OUT + c2]);
            __half2 v1 = __ldg((const __half2*)&g_sup2h[(size_t)e1.x * F_OUT + c2]);
            float2 f0 = __half22float2(v0);
            float2 f1 = __half22float2(v1);
            a0 += w0 * f0.x + w1 * f1.x;
            a1 += w0 * f0.y + w1 * f1.y;
        }
    }
    if (j < e) {
        int2 e0 = __ldcs(&g_epack[j]);
        float w0 = __int_as_float(e0.y);
        if (act) {
            __half2 v0 = __ldg((const __half2*)&g_sup2h[(size_t)e0.x * F_OUT + c2]);
            float2 f0 = __half22float2(v0);
            a0 += w0 * f0.x;
            a1 += w0 * f0.y;
        }
    }
    float x0 = act ? a0 : -3.0e38f;
    float x1 = act ? a1 : -3.0e38f;
    float m = fmaxf(x0, x1);
#pragma unroll
    for (int off = 16; off; off >>= 1) m = fmaxf(m, __shfl_xor_sync(0xffffffffu, m, off));
    float sum = act ? (expf(x0 - m) + expf(x1 - m)) : 0.f;
#pragma unroll
    for (int off = 16; off; off >>= 1) sum += __shfl_xor_sync(0xffffffffu, sum, off);
    float ls = logf(sum);
    if (act) {
        float2 o = make_float2(x0 - m - ls, x1 - m - ls);
        *(float2*)(&out[(size_t)r * F_OUT + c2]) = o;
    }
}

// ============================================================
extern "C" void kernel_launch(void* const* d_in, const int* in_sizes, int n_in,
                              void* d_out, int out_size) {
    const float* x  = (const float*)d_in[0];
    const int*   ei = (const int*)d_in[1];
    const float* ew = (const float*)d_in[2];
    const float* W1 = (const float*)d_in[3];
    const float* W2 = (const float*)d_in[4];
    float* out = (float*)d_out;

    // Fork a second stream so GEMM1 (tensor/DRAM) overlaps the CSR build
    // (atomics/L2). Host objects only; kernel_launch runs a handful of times.
    cudaStream_t s2;
    cudaStreamCreateWithFlags(&s2, cudaStreamNonBlocking);
    cudaEvent_t evFork, evJoin;
    cudaEventCreateWithFlags(&evFork, cudaEventDisableTiming);
    cudaEventCreateWithFlags(&evJoin, cudaEventDisableTiming);

    detect_dtype_kernel<<<1, 32>>>(ei);
    zero_deg_kernel<<<(N_NODES + 256) / 256, 256>>>();

    // fork: GEMM1 branch on s2 — sgemm1 stays the 4th submitted launch (profiled)
    cudaEventRecord(evFork, 0);
    cudaStreamWaitEvent(s2, evFork, 0);
    w1t_kernel<<<(F_IN * F_HID + 255) / 256, 256, 0, s2>>>(W1);
    sgemm1_f16_kernel<<<(N_NODES + 63) / 64, 256, 0, s2>>>(x);

    // CSR build branch on capture stream
    hist_kernel<<<(E_EDGES + 255) / 256, 256>>>(ei);
    scan_blocks_kernel<<<NBLK, 256>>>();
    scan_bsum_kernel<<<1, 512>>>();
    scan_add_kernel<<<NBLK, 256>>>();
    fill_kernel<<<(E_EDGES + 255) / 256, 256>>>(ei, ew);

    // join
    cudaEventRecord(evJoin, s2);
    cudaStreamWaitEvent(0, evJoin, 0);

    spmm1_relu_kernel<<<(N_NODES + 7) / 8, 256>>>();
    gemm2_kernel<<<(N_NODES + 63) / 64, 256>>>(W2);
    spmm2_lsm_kernel<<<(N_NODES + 7) / 8, 256>>>(out);
}

// round 17
// speedup vs baseline: 1.0328x; 1.0328x over previous
#include <cuda_runtime.h>
#include <cuda_fp16.h>
#include <math.h>
#include <stdint.h>

#define N_NODES 100000
#define E_EDGES 3200000
#define F_IN    512
#define F_HID   256
#define F_OUT   40
#define NBLK    391   // ceil(N_NODES/256)

// ---- scratch (static device globals; no runtime allocation) ----
// g_deg relies on zero-initialization at module load; fill_kernel re-zeros it
// at the end of every launch so each subsequent launch sees deg == 0.
__device__ __align__(16) __half g_sup1h[(size_t)N_NODES * F_HID]; // x @ W1 (fp16)
__device__ __align__(16) __half g_w1t[(size_t)F_HID * F_IN];      // W1^T fp16 [N][K]
__device__ __align__(16) __half g_hh[(size_t)N_NODES * F_HID];    // relu(A @ sup1) fp16
__device__ __align__(16) __half g_sup2h[(size_t)N_NODES * F_OUT]; // h @ W2 fp16
__device__ int   g_deg[N_NODES + 1];
__device__ int   g_rowptr[N_NODES + 1];
__device__ int   g_cursor[N_NODES];
__device__ int   g_bsum[512];
__device__ int2  g_epack[E_EDGES];                  // (src, weight bits), dst-grouped
__device__ int   g_is64;   // 1 if edge_index buffer is actually int64

// ============================================================
// prep: dtype probe (block 0) + W1 transpose/fp16 convert (all blocks)
// ============================================================
__global__ void prep_kernel(const float* __restrict__ W1,
                            const int* __restrict__ ei) {
    if (blockIdx.x == 0 && threadIdx.x < 32) {
        bool allz = true;
        for (int i = threadIdx.x; i < 64; i += 32)
            if (ei[2 * i + 1] != 0) allz = false;
        allz = __all_sync(0xffffffffu, allz);
        if (threadIdx.x == 0) g_is64 = allz ? 1 : 0;
    }
    int idx = blockIdx.x * 256 + threadIdx.x;   // over 512*256 = 131072
    if (idx < F_IN * F_HID) {
        int k = idx / F_HID, n = idx % F_HID;
        g_w1t[(size_t)n * F_IN + k] = __float2half_rn(W1[idx]);
    }
}

__device__ __forceinline__ int load_src(const int* ei, int e, int is64) {
    return is64 ? ei[2 * (size_t)e] : ei[e];
}
__device__ __forceinline__ int load_dst(const int* ei, int e, int is64) {
    return is64 ? ei[2 * ((size_t)E_EDGES + e)] : ei[(size_t)E_EDGES + e];
}

// ============================================================
// CSR construction (dst-sorted adjacency, built every launch)
// ============================================================
__global__ void hist_kernel(const int* __restrict__ ei) {
    int e = blockIdx.x * blockDim.x + threadIdx.x;
    if (e >= E_EDGES) return;
    int is64 = g_is64;
    unsigned d = (unsigned)load_dst(ei, e, is64);
    if (d < N_NODES) atomicAdd(&g_deg[d], 1);
}

// phase 1: per-block (256) scan; write within-block exclusive + block sum
__global__ void scan_blocks_kernel() {
    int tid = threadIdx.x;
    int i = blockIdx.x * 256 + tid;
    int v = (i < N_NODES) ? g_deg[i] : 0;
    int lane = tid & 31, w = tid >> 5;
    int x = v;
#pragma unroll
    for (int off = 1; off < 32; off <<= 1) {
        int t = __shfl_up_sync(0xffffffffu, x, off);
        if (lane >= off) x += t;
    }
    __shared__ int ws[8];
    if (lane == 31) ws[w] = x;
    __syncthreads();
    if (w == 0) {
        int y = (lane < 8) ? ws[lane] : 0;
#pragma unroll
        for (int off = 1; off < 8; off <<= 1) {
            int t = __shfl_up_sync(0xffffffffu, y, off);
            if (lane >= off) y += t;
        }
        if (lane < 8) ws[lane] = y;
    }
    __syncthreads();
    int incl = x + (w > 0 ? ws[w - 1] : 0);
    if (i < N_NODES) g_rowptr[i] = incl - v;
    if (tid == 255) g_bsum[blockIdx.x] = incl;
}

// phase 2 (fused): each block REDUCES bsum[0..b) for its own offset,
// adds to its rowptr tile, writes cursor. Block 0 also writes rowptr[N]
// (full-array reduction; its own offset is 0).
__global__ void scan_finish_kernel() {
    int b = blockIdx.x, tid = threadIdx.x;
    int lane = tid & 31, w = tid >> 5;
    int acc = 0;
    for (int i = tid; i < NBLK; i += 256) {
        int bv = g_bsum[i];
        if (b == 0 || i < b) acc += bv;   // block 0: full sum (for total)
    }
#pragma unroll
    for (int off = 16; off; off >>= 1) acc += __shfl_xor_sync(0xffffffffu, acc, off);
    __shared__ int ws[8];
    if (lane == 0) ws[w] = acc;
    __syncthreads();
    if (w == 0) {
        int y = (lane < 8) ? ws[lane] : 0;
#pragma unroll
        for (int off = 4; off; off >>= 1) y += __shfl_xor_sync(0xffffffffu, y, off);
        if (lane == 0) ws[0] = y;
    }
    __syncthreads();
    int red = ws[0];
    int offset = (b == 0) ? 0 : red;
    if (b == 0 && tid == 0) g_rowptr[N_NODES] = red;
    int i2 = b * 256 + tid;
    if (i2 < N_NODES) {
        int r = g_rowptr[i2] + offset;
        g_rowptr[i2] = r;
        g_cursor[i2] = r;
    }
}

__global__ void fill_kernel(const int* __restrict__ ei,
                            const float* __restrict__ ew) {
    int e = blockIdx.x * blockDim.x + threadIdx.x;
    // re-zero deg for the NEXT launch (scans already consumed it this launch)
    if (e <= N_NODES) g_deg[e] = 0;
    if (e >= E_EDGES) return;
    int is64 = g_is64;
    unsigned s = (unsigned)load_src(ei, e, is64);
    unsigned d = (unsigned)load_dst(ei, e, is64);
    if (d >= N_NODES || s >= N_NODES) return;
    int p = atomicAdd(&g_cursor[d], 1);
    if (p < E_EDGES)
        g_epack[p] = make_int2((int)s, __float_as_int(ew[e]));
}

// ============================================================
// GEMM1 (fp16 tensor cores): sup1h = x[100000,512] @ W1[512,256]
// block tile 64x256, BK=32, double-buffered smem pipeline
// (256 threads, 2 blocks/SM — best measured: ~100 us)
// ============================================================
#define LDSM_X4(r0, r1, r2, r3, addr) \
    asm volatile("ldmatrix.sync.aligned.m8n8.x4.shared.b16 {%0,%1,%2,%3}, [%4];" \
        : "=r"(r0), "=r"(r1), "=r"(r2), "=r"(r3) : "r"(addr))

__device__ __forceinline__ void cp_async16(uint32_t dst, const void* src) {
    asm volatile("cp.async.cg.shared.global [%0], [%1], 16;" :: "r"(dst), "l"(src));
}
#define CP_COMMIT() asm volatile("cp.async.commit_group;")
#define CP_WAIT0()  asm volatile("cp.async.wait_group 0;" ::: "memory")

__global__ __launch_bounds__(256) void sgemm1_f16_kernel(const float* __restrict__ A) {
    __shared__ __half As[2][64][32];    //  8 KB
    __shared__ __half Bs[2][256][32];   // 32 KB
    const int A_BUF = 64 * 32 * 2;      // bytes
    const int B_BUF = 256 * 32 * 2;
    int tid = threadIdx.x;
    int warp = tid >> 5, lane = tid & 31;
    int wm = (warp & 1) * 32;      // 2 m-warps
    int wn = (warp >> 1) * 64;     // 4 n-warps
    int blockRow = blockIdx.x * 64;

    float acc[2][8][4];
#pragma unroll
    for (int mt = 0; mt < 2; mt++)
#pragma unroll
        for (int nt = 0; nt < 8; nt++)
#pragma unroll
            for (int q = 0; q < 4; q++) acc[mt][nt][q] = 0.f;

    // staging mapping
    int sm_m = tid >> 2;                 // A row 0..63
    int sm_c = tid & 3;                  // 16B chunk 0..3
    int a_st_off = (sm_m * 32 + (sm_c ^ ((sm_m >> 1) & 3)) * 8) * 2;
    int gm = blockRow + sm_m;
    if (gm >= N_NODES) gm = N_NODES - 1;
    const float* Arow = A + (size_t)gm * F_IN + sm_c * 8;

    uint32_t a_base = (uint32_t)__cvta_generic_to_shared(&As[0][0][0]);
    uint32_t b_base = (uint32_t)__cvta_generic_to_shared(&Bs[0][0][0]);

    // B staging: 4 rows per thread (n = tid>>2 + 64*i), chunk = tid&3
    int b_n0 = tid >> 2;
    uint32_t b_st[4];
    const __half* b_src[4];
#pragma unroll
    for (int i = 0; i < 4; i++) {
        int n = b_n0 + 64 * i;
        b_st[i] = b_base + (uint32_t)((n * 32 + (sm_c ^ ((n >> 1) & 3)) * 8) * 2);
        b_src[i] = &g_w1t[(size_t)n * F_IN + sm_c * 8];
    }

    // ldmatrix per-lane mapping
    int mat = lane >> 3;             // 0..3
    int mrow = lane & 7;
    int a_row_off = (mat & 1) * 8 + mrow;
    int a_chunk   = (mat >> 1);
    int b_row_off = ((mat >> 1) & 1) * 8 + mrow;
    int b_chunk   = (mat & 1);

    // ---- prologue: stage tile 0 ----
    {
        float4 v0 = *(const float4*)(Arow);
        float4 v1 = *(const float4*)(Arow + 4);
        __half2 p0 = __floats2half2_rn(v0.x, v0.y);
        __half2 p1 = __floats2half2_rn(v0.z, v0.w);
        __half2 p2 = __floats2half2_rn(v1.x, v1.y);
        __half2 p3 = __floats2half2_rn(v1.z, v1.w);
        *(uint4*)((char*)&As[0][0][0] + a_st_off) =
            make_uint4(*(uint32_t*)&p0, *(uint32_t*)&p1,
                       *(uint32_t*)&p2, *(uint32_t*)&p3);
#pragma unroll
        for (int i = 0; i < 4; i++) cp_async16(b_st[i], b_src[i]);
        CP_COMMIT();
        CP_WAIT0();
    }
    __syncthreads();

    const int NIT = F_IN / 32;   // 16
    for (int it = 0; it < NIT; it++) {
        int cur = it & 1, nxt = cur ^ 1;
        bool has_next = (it + 1 < NIT);
        float4 na0, na1;
        if (has_next) {
            int k1 = (it + 1) * 32;
            na0 = *(const float4*)(Arow + k1);       // LDG issued early
            na1 = *(const float4*)(Arow + k1 + 4);
#pragma unroll
            for (int i = 0; i < 4; i++)
                cp_async16(b_st[i] + (uint32_t)(nxt * B_BUF), b_src[i] + k1);
            CP_COMMIT();
        }

        // ---- compute on buffer cur ----
        uint32_t ab = a_base + cur * A_BUF;
        uint32_t bb = b_base + cur * B_BUF;
#pragma unroll
        for (int kk = 0; kk < 32; kk += 16) {
            int kc = kk >> 3;                         // 0 or 2
            uint32_t af[2][4];
#pragma unroll
            for (int mt = 0; mt < 2; mt++) {
                int r = wm + mt * 16 + a_row_off;
                int ch = (kc + a_chunk) ^ ((r >> 1) & 3);
                LDSM_X4(af[mt][0], af[mt][1], af[mt][2], af[mt][3],
                        ab + (uint32_t)((r * 32 + ch * 8) * 2));
            }
            uint32_t bf[8][2];
#pragma unroll
            for (int np = 0; np < 4; np++) {
                int n = wn + np * 16 + b_row_off;
                int ch = (kc + b_chunk) ^ ((n >> 1) & 3);
                LDSM_X4(bf[2 * np][0], bf[2 * np][1],
                        bf[2 * np + 1][0], bf[2 * np + 1][1],
                        bb + (uint32_t)((n * 32 + ch * 8) * 2));
            }
#pragma unroll
            for (int mt = 0; mt < 2; mt++)
#pragma unroll
                for (int nt = 0; nt < 8; nt++) {
                    asm volatile(
                        "mma.sync.aligned.m16n8k16.row.col.f32.f16.f16.f32 "
                        "{%0,%1,%2,%3}, {%4,%5,%6,%7}, {%8,%9}, {%0,%1,%2,%3};\n"
                        : "+f"(acc[mt][nt][0]), "+f"(acc[mt][nt][1]),
                          "+f"(acc[mt][nt][2]), "+f"(acc[mt][nt][3])
                        : "r"(af[mt][0]), "r"(af[mt][1]), "r"(af[mt][2]), "r"(af[mt][3]),
                          "r"(bf[nt][0]), "r"(bf[nt][1]));
                }
        }

        if (has_next) {
            __half2 p0 = __floats2half2_rn(na0.x, na0.y);
            __half2 p1 = __floats2half2_rn(na0.z, na0.w);
            __half2 p2 = __floats2half2_rn(na1.x, na1.y);
            __half2 p3 = __floats2half2_rn(na1.z, na1.w);
            *(uint4*)((char*)&As[0][0][0] + nxt * A_BUF + a_st_off) =
                make_uint4(*(uint32_t*)&p0, *(uint32_t*)&p1,
                           *(uint32_t*)&p2, *(uint32_t*)&p3);
            CP_WAIT0();
        }
        __syncthreads();
    }

    int lk = lane & 3, lr = lane >> 2;
#pragma unroll
    for (int mt = 0; mt < 2; mt++)
#pragma unroll
        for (int nt = 0; nt < 8; nt++) {
            int r0 = blockRow + wm + mt * 16 + lr;
            int cn = wn + nt * 8 + lk * 2;
            if (r0 < N_NODES)
                *(__half2*)(&g_sup1h[(size_t)r0 * F_HID + cn]) =
                    __floats2half2_rn(acc[mt][nt][0], acc[mt][nt][1]);
            int r1 = r0 + 8;
            if (r1 < N_NODES)
                *(__half2*)(&g_sup1h[(size_t)r1 * F_HID + cn]) =
                    __floats2half2_rn(acc[mt][nt][2], acc[mt][nt][3]);
        }
}

// ============================================================
// SPMM1 + ReLU: h[d,:] = relu(sum_j w_j * sup1h[src_j,:]),  256 feats fp16
// warp per dst row; 8 feats/lane; 4-edge unroll (measured best)
// ============================================================
__device__ __forceinline__ void acc8(float* acc, uint4 v, float w) {
    const __half2* h2 = (const __half2*)&v;
#pragma unroll
    for (int i = 0; i < 4; i++) {
        float2 f = __half22float2(h2[i]);
        acc[2 * i]     += w * f.x;
        acc[2 * i + 1] += w * f.y;
    }
}

__global__ __launch_bounds__(256) void spmm1_relu_kernel() {
    int warp = threadIdx.x >> 5, lane = threadIdx.x & 31;
    int d = blockIdx.x * 8 + warp;
    if (d >= N_NODES) return;
    int s = g_rowptr[d], e = g_rowptr[d + 1];
    float acc[8];
#pragma unroll
    for (int i = 0; i < 8; i++) acc[i] = 0.f;
    const uint4* base = (const uint4*)g_sup1h;   // 16B units; row = 32 units
    int j = s;
    for (; j + 3 < e; j += 4) {
        int2 ep[4];
        uint4 v[4];
#pragma unroll
        for (int q = 0; q < 4; q++) ep[q] = g_epack[j + q];
#pragma unroll
        for (int q = 0; q < 4; q++)
            v[q] = __ldg(base + (size_t)ep[q].x * (F_HID / 8) + lane);
#pragma unroll
        for (int q = 0; q < 4; q++)
            acc8(acc, v[q], __int_as_float(ep[q].y));
    }
    for (; j < e; j++) {
        int2 e0 = g_epack[j];
        uint4 v0 = __ldg(base + (size_t)e0.x * (F_HID / 8) + lane);
        acc8(acc, v0, __int_as_float(e0.y));
    }
    __half2 o[4];
#pragma unroll
    for (int i = 0; i < 4; i++)
        o[i] = __floats2half2_rn(fmaxf(acc[2 * i], 0.f), fmaxf(acc[2 * i + 1], 0.f));
    *(uint4*)(&g_hh[(size_t)d * F_HID + lane * 8]) =
        make_uint4(*(uint32_t*)&o[0], *(uint32_t*)&o[1],
                   *(uint32_t*)&o[2], *(uint32_t*)&o[3]);
}

// ============================================================
// GEMM2: sup2h[100000,40] = h[100000,256] @ W2[256,40]  (h fp16)
// 8 rows/warp (4 FMA per shared load); hh consumed as uint4
// ============================================================
__global__ __launch_bounds__(256) void gemm2_kernel(const float* __restrict__ W2) {
    __shared__ float sW[F_HID * F_OUT];   // 40 KB
    int tid = threadIdx.x;
    for (int i = tid; i < F_HID * F_OUT; i += 256) sW[i] = W2[i];
    __syncthreads();
    int warp = tid >> 5, lane = tid & 31;
    int r0 = blockIdx.x * 64 + warp * 8;
    if (r0 >= N_NODES) return;
    int rr[8];
#pragma unroll
    for (int i = 0; i < 8; i++) {
        rr[i] = r0 + i;
        if (rr[i] >= N_NODES) rr[i] = N_NODES - 1;
    }
    float a0[8], a1[8];
#pragma unroll
    for (int i = 0; i < 8; i++) { a0[i] = 0.f; a1[i] = 0.f; }
    int l8 = 32 + (lane & 7);
    for (int k0 = 0; k0 < F_HID; k0 += 8) {
        uint4 hv[8];
#pragma unroll
        for (int i = 0; i < 8; i++)
            hv[i] = __ldg((const uint4*)&g_hh[(size_t)rr[i] * F_HID + k0]);
#pragma unroll
        for (int kk = 0; kk < 8; kk += 2) {
            float b00 = sW[(k0 + kk) * F_OUT + lane];
            float b01 = sW[(k0 + kk) * F_OUT + l8];
            float b10 = sW[(k0 + kk + 1) * F_OUT + lane];
            float b11 = sW[(k0 + kk + 1) * F_OUT + l8];
#pragma unroll
            for (int i = 0; i < 8; i++) {
                __half2 h2 = ((const __half2*)&hv[i])[kk >> 1];
                float2 hf = __half22float2(h2);
                a0[i] += hf.x * b00 + hf.y * b10;
                a1[i] += hf.x * b01 + hf.y * b11;
            }
        }
    }
#pragma unroll
    for (int i = 0; i < 8; i++) {
        int r = r0 + i;
        if (r < N_NODES) {
            g_sup2h[(size_t)r * F_OUT + lane] = __float2half_rn(a0[i]);
            if (lane < 8) g_sup2h[(size_t)r * F_OUT + 32 + lane] = __float2half_rn(a1[i]);
        }
    }
}

// ============================================================
// Fused SPMM2 + log_softmax: warp per dst row (sup2 fp16)
// lane c (<20) covers classes {2c, 2c+1} via ONE half2 load per edge
// ============================================================
__global__ __launch_bounds__(256) void spmm2_lsm_kernel(float* __restrict__ out) {
    int warp = threadIdx.x >> 5, lane = threadIdx.x & 31;
    int r = blockIdx.x * 8 + warp;
    if (r >= N_NODES) return;
    int s = g_rowptr[r], e = g_rowptr[r + 1];
    bool act = (lane < F_OUT / 2);     // 20 active lanes
    int c2 = lane * 2;                 // class pair base
    float a0 = 0.f, a1 = 0.f;
    int j = s;
    for (; j + 1 < e; j += 2) {
        int2 e0 = g_epack[j], e1 = g_epack[j + 1];
        float w0 = __int_as_float(e0.y), w1 = __int_as_float(e1.y);
        if (act) {
            __half2 v0 = __ldg((const __half2*)&g_sup2h[(size_t)e0.x * F_OUT + c2]);
            __half2 v1 = __ldg((const __half2*)&g_sup2h[(size_t)e1.x * F_OUT + c2]);
            float2 f0 = __half22float2(v0);
            float2 f1 = __half22float2(v1);
            a0 += w0 * f0.x + w1 * f1.x;
            a1 += w0 * f0.y + w1 * f1.y;
        }
    }
    if (j < e) {
        int2 e0 = g_epack[j];
        float w0 = __int_as_float(e0.y);
        if (act) {
            __half2 v0 = __ldg((const __half2*)&g_sup2h[(size_t)e0.x * F_OUT + c2]);
            float2 f0 = __half22float2(v0);
            a0 += w0 * f0.x;
            a1 += w0 * f0.y;
        }
    }
    float x0 = act ? a0 : -3.0e38f;
    float x1 = act ? a1 : -3.0e38f;
    float m = fmaxf(x0, x1);
#pragma unroll
    for (int off = 16; off; off >>= 1) m = fmaxf(m, __shfl_xor_sync(0xffffffffu, m, off));
    float sum = act ? (expf(x0 - m) + expf(x1 - m)) : 0.f;
#pragma unroll
    for (int off = 16; off; off >>= 1) sum += __shfl_xor_sync(0xffffffffu, sum, off);
    float ls = logf(sum);
    if (act) {
        float2 o = make_float2(x0 - m - ls, x1 - m - ls);
        *(float2*)(&out[(size_t)r * F_OUT + c2]) = o;
    }
}

// ============================================================
extern "C" void kernel_launch(void* const* d_in, const int* in_sizes, int n_in,
                              void* d_out, int out_size) {
    const float* x  = (const float*)d_in[0];
    const int*   ei = (const int*)d_in[1];
    const float* ew = (const float*)d_in[2];
    const float* W1 = (const float*)d_in[3];
    const float* W2 = (const float*)d_in[4];
    float* out = (float*)d_out;

    // Two-stream fork: GEMM1 (tensor/DRAM) overlaps CSR build (atomics/L2).
    cudaStream_t s2;
    cudaStreamCreateWithFlags(&s2, cudaStreamNonBlocking);
    cudaEvent_t evFork, evJoin;
    cudaEventCreateWithFlags(&evFork, cudaEventDisableTiming);
    cudaEventCreateWithFlags(&evJoin, cudaEventDisableTiming);

    // (1) probe + w1t in one kernel; fork immediately after
    prep_kernel<<<512, 256>>>(W1, ei);
    cudaEventRecord(evFork, 0);
    cudaStreamWaitEvent(s2, evFork, 0);
    // (2) GEMM1 on s2
    sgemm1_f16_kernel<<<(N_NODES + 63) / 64, 256, 0, s2>>>(x);

    // CSR build on capture stream (deg was zeroed by previous launch's fill,
    // or by static zero-init on the very first call)
    hist_kernel<<<(E_EDGES + 255) / 256, 256>>>(ei);        // (3)
    scan_blocks_kernel<<<NBLK, 256>>>();                    // (4)
    scan_finish_kernel<<<NBLK, 256>>>();                    // (5)
    fill_kernel<<<(E_EDGES + 255) / 256, 256>>>(ei, ew);    // (6) + deg re-zero

    // join
    cudaEventRecord(evJoin, s2);
    cudaStreamWaitEvent(0, evJoin, 0);

    spmm1_relu_kernel<<<(N_NODES + 7) / 8, 256>>>();        // (7)
    gemm2_kernel<<<(N_NODES + 63) / 64, 256>>>(W2);         // (8)
    spmm2_lsm_kernel<<<(N_NODES + 7) / 8, 256>>>(out);      // (9)
}